// round 6
// baseline (speedup 1.0000x reference)
#include <cuda_runtime.h>
#include <cstdint>

#define BB 32
#define SS 128
#define KN 12
#define KC 10
#define KT 22
#define DD 200
#define D4 50
#define CC 45
#define CP 48
#define CP4 12
#define FF 1000
#define NTOK 4096

#define GT 32
#define NTILES (NTOK / GT)                 // 128
#define APAD 51                            // shA pitch in float4

#define FTOK 4                             // tokens per feat block (1 warp each)
#define FEATB (NTOK / FTOK)                // 1024
#define ROWB 800                           // bytes per embedding row
#define TOKSLOT (KT * ROWB)                // 17600 B staging per token
#define FEAT_SMEM (512 + FTOK * TOKSLOT)   // 70912 B dynamic smem

__device__ float g_feat[NTOK * DD];
__device__ float g_part[5 * NTOK * CP];

// ---------------------------------------------------------------------------
// Kernel 1: feat gather via TMA bulk copies (bypasses L1tex LDG queue cap).
// Block = 4 tokens, 1 warp per token. Warp compacts active ids, issues one
// cp.async.bulk (800B) per active row into smem, waits on mbarrier
// (expect_tx = n*800), then reduces rows from smem.
// ---------------------------------------------------------------------------
__global__ void __launch_bounds__(128)
feat_kernel(const int* __restrict__ ngram_ids,
            const int* __restrict__ ngram_mask,
            const int* __restrict__ ctx_ids,
            const int* __restrict__ ctx_mask,
            const float* __restrict__ embed) {
    extern __shared__ char smem[];
    // layout: [0,32) mbar[4], [32,48) cnt[4], [64,448) act[4][24], [512,..) rows
    uint64_t* mbar = (uint64_t*)smem;
    int* s_cnt = (int*)(smem + 32);
    int (*s_act)[24] = (int (*)[24])(smem + 64);

    uint32_t smem_u32;
    asm("{ .reg .u64 t; cvta.to.shared.u64 t, %1; cvt.u32.u64 %0, t; }"
        : "=r"(smem_u32) : "l"(smem));

    const int wid  = threadIdx.x >> 5;       // token group 0..3
    const int lane = threadIdx.x & 31;
    const int tok  = blockIdx.x * FTOK + wid;

    // ---- compact active ids ----
    int m = 0, id = 0;
    if (lane < KN) {
        id = ngram_ids[tok * KN + lane];
        m  = ngram_mask[tok * KN + lane];
    } else if (lane < KT) {
        id = ctx_ids[tok * KC + lane - KN];
        m  = ctx_mask[tok * KC + lane - KN];
    }
    unsigned bal = __ballot_sync(0xffffffffu, m != 0);
    if (m) s_act[wid][__popc(bal & ((1u << lane) - 1u))] = id;
    const int n = __popc(bal);
    if (lane == 0) s_cnt[wid] = n;

    // ---- init mbarrier, issue TMA bulk copies ----
    if (lane == 0) {
        uint32_t mb = smem_u32 + wid * 8;
        asm volatile("mbarrier.init.shared.b64 [%0], 1;" :: "r"(mb) : "memory");
        asm volatile("fence.proxy.async.shared::cta;" ::: "memory");
        if (n > 0) {
            asm volatile("mbarrier.arrive.expect_tx.shared.b64 _, [%0], %1;"
                         :: "r"(mb), "r"(n * ROWB) : "memory");
            uint32_t dst0 = smem_u32 + 512 + wid * TOKSLOT;
            for (int r = 0; r < n; r++) {
                const char* src = (const char*)embed + (long long)s_act[wid][r] * ROWB;
                asm volatile(
                    "cp.async.bulk.shared::cta.global.mbarrier::complete_tx::bytes "
                    "[%0], [%1], %2, [%3];"
                    :: "r"(dst0 + r * ROWB), "l"(src), "r"(ROWB), "r"(mb)
                    : "memory");
            }
        }
    }
    __syncwarp();

    if (n > 0) {
        uint32_t mb = smem_u32 + wid * 8;
        uint32_t done;
        do {
            asm volatile(
                "{ .reg .pred p;"
                "  mbarrier.try_wait.parity.acquire.cta.shared::cta.b64 p, [%1], 0, 0x989680;"
                "  selp.b32 %0, 1, 0, p; }"
                : "=r"(done) : "r"(mb) : "memory");
        } while (!done);
    }

    // ---- reduce staged rows: lane handles float4 cols lane, lane+32 ----
    const float4* rows = (const float4*)(smem + 512 + wid * TOKSLOT);
    const float inv = 1.0f / (float)(n > 0 ? n : 1);
    float4* gout = (float4*)g_feat + (long long)tok * D4;

    #pragma unroll
    for (int round = 0; round < 2; round++) {
        int col = round * 32 + lane;
        if (col < D4) {
            float ax = 0.f, ay = 0.f, az = 0.f, aw = 0.f;
            int r = 0;
            for (; r + 4 <= n; r += 4) {
                float4 v0 = rows[(r + 0) * D4 + col];
                float4 v1 = rows[(r + 1) * D4 + col];
                float4 v2 = rows[(r + 2) * D4 + col];
                float4 v3 = rows[(r + 3) * D4 + col];
                ax += (v0.x + v1.x) + (v2.x + v3.x);
                ay += (v0.y + v1.y) + (v2.y + v3.y);
                az += (v0.z + v1.z) + (v2.z + v3.z);
                aw += (v0.w + v1.w) + (v2.w + v3.w);
            }
            for (; r < n; r++) {
                float4 v = rows[r * D4 + col];
                ax += v.x; ay += v.y; az += v.z; aw += v.w;
            }
            float4 o; o.x = ax * inv; o.y = ay * inv; o.z = az * inv; o.w = aw * inv;
            gout[col] = o;
        }
    }
}

// ---------------------------------------------------------------------------
// Kernel 2: per-window partial GEMM, B transposed on the fly from W.
// ---------------------------------------------------------------------------
__global__ void __launch_bounds__(384)
gemm_kernel(const float* __restrict__ W) {
    __shared__ float4 shA[GT * APAD];        // 26112 B
    __shared__ float4 shB[100 * CP4];        // 19200 B
    float* shBf = (float*)shB;

    const int tile = blockIdx.x;
    const int w = blockIdx.y;
    const int tokBase = tile * GT;
    const int b  = tokBase / SS;
    const int s0 = tokBase % SS;

    const int tid = threadIdx.x;
    const int lane = tid & 31;
    const int upper = tid >> 5;
    const int tg = (lane & 15) + 16 * (upper & 1);
    const int cg = (upper >> 1) * 2 + (lane >> 4);

    const float4* gf4 = (const float4*)g_feat;
    for (int i = tid; i < GT * D4; i += 384) {
        int r  = i / D4;
        int dv = i - r * D4;
        int s  = s0 + w - 2 + r;
        float4 v = make_float4(0.f, 0.f, 0.f, 0.f);
        if (s >= 0 && s < SS) v = gf4[(b * SS + s) * D4 + dv];
        shA[r * APAD + dv] = v;
    }

    float acc0 = 0.f, acc1 = 0.f, acc2 = 0.f, acc3 = 0.f;

    #pragma unroll
    for (int h = 0; h < 2; h++) {
        __syncthreads();
        for (int i = tid; i < 100 * CP; i += 384) {
            int c  = i / 100;
            int kk = i - c * 100;
            shBf[kk * CP + c] = (c < CC) ? W[c * FF + w * DD + h * 100 + kk] : 0.0f;
        }
        __syncthreads();

        const float4* aRow = &shA[tg * APAD + h * 25];
        #pragma unroll
        for (int dq = 0; dq < 25; dq++) {
            float4 a  = aRow[dq];
            float4 b0 = shB[(dq * 4 + 0) * CP4 + cg];
            float4 b1 = shB[(dq * 4 + 1) * CP4 + cg];
            float4 b2 = shB[(dq * 4 + 2) * CP4 + cg];
            float4 b3 = shB[(dq * 4 + 3) * CP4 + cg];
            acc0 = fmaf(a.x, b0.x, acc0); acc1 = fmaf(a.x, b0.y, acc1);
            acc2 = fmaf(a.x, b0.z, acc2); acc3 = fmaf(a.x, b0.w, acc3);
            acc0 = fmaf(a.y, b1.x, acc0); acc1 = fmaf(a.y, b1.y, acc1);
            acc2 = fmaf(a.y, b1.z, acc2); acc3 = fmaf(a.y, b1.w, acc3);
            acc0 = fmaf(a.z, b2.x, acc0); acc1 = fmaf(a.z, b2.y, acc1);
            acc2 = fmaf(a.z, b2.z, acc2); acc3 = fmaf(a.z, b2.w, acc3);
            acc0 = fmaf(a.w, b3.x, acc0); acc1 = fmaf(a.w, b3.y, acc1);
            acc2 = fmaf(a.w, b3.z, acc2); acc3 = fmaf(a.w, b3.w, acc3);
        }
    }

    float4 v; v.x = acc0; v.y = acc1; v.z = acc2; v.w = acc3;
    ((float4*)g_part)[((long long)w * NTOK + tokBase + tg) * CP4 + cg] = v;
}

// ---------------------------------------------------------------------------
// Kernel 3: reduce 5 partials (float4) + bias -> out [tok, 45]
// ---------------------------------------------------------------------------
__global__ void reduce_kernel(const float* __restrict__ bias,
                              float* __restrict__ out) {
    int i = blockIdx.x * blockDim.x + threadIdx.x;
    if (i >= NTOK * CP4) return;
    int tok = i / CP4;
    int cg  = i - tok * CP4;
    const float4* p4 = (const float4*)g_part;
    float4 s = make_float4(0.f, 0.f, 0.f, 0.f);
    #pragma unroll
    for (int w = 0; w < 5; w++) {
        float4 v = p4[((long long)w * NTOK + tok) * CP4 + cg];
        s.x += v.x; s.y += v.y; s.z += v.z; s.w += v.w;
    }
    int c0 = cg * 4;
    float* o = out + (long long)tok * CC;
    if (c0 + 0 < CC) o[c0 + 0] = s.x + bias[c0 + 0];
    if (c0 + 1 < CC) o[c0 + 1] = s.y + bias[c0 + 1];
    if (c0 + 2 < CC) o[c0 + 2] = s.z + bias[c0 + 2];
    if (c0 + 3 < CC) o[c0 + 3] = s.w + bias[c0 + 3];
}

// ---------------------------------------------------------------------------
extern "C" void kernel_launch(void* const* d_in, const int* in_sizes, int n_in,
                              void* d_out, int out_size) {
    const int*   ngram_ids  = (const int*)d_in[0];
    const int*   ngram_mask = (const int*)d_in[1];
    const int*   ctx_ids    = (const int*)d_in[2];
    const int*   ctx_mask   = (const int*)d_in[3];
    const float* embed      = (const float*)d_in[4];
    const float* W          = (const float*)d_in[5];
    const float* bias       = (const float*)d_in[6];
    float* out = (float*)d_out;

    static bool attr_set = false;
    if (!attr_set) {
        cudaFuncSetAttribute(feat_kernel,
                             cudaFuncAttributeMaxDynamicSharedMemorySize, FEAT_SMEM);
        attr_set = true;
    }

    feat_kernel<<<FEATB, 128, FEAT_SMEM>>>(
        ngram_ids, ngram_mask, ctx_ids, ctx_mask, embed);
    gemm_kernel<<<dim3(NTILES, 5), 384>>>(W);
    reduce_kernel<<<(NTOK * CP4 + 255) / 256, 256>>>(bias, out);
}